// round 1
// baseline (speedup 1.0000x reference)
#include <cuda_runtime.h>
#include <cstdint>

typedef unsigned long long ull;

#define B_TOTAL 131072
#define T_STEPS 30
#define DIN     88
#define H       20
#define G       (4*H)     // 80 gate outputs
#define NP      (G/2)     // 40 packed pairs
#define CTA     128
#define XS_STRIDE (CTA+1) // 129, bank-conflict-free

// ---------------- shared memory layout ----------------
struct SM {
    float2 w0x[DIN * NP];   // layer0 input weights, transposed+paired: [d][j2] = (W[2j2][d], W[2j2+1][d])
    float2 w0h[H * NP];     // layer0 recurrent weights
    float2 w1x[H * NP];     // layer1 input (h0) weights
    float2 w1h[H * NP];     // layer1 recurrent weights
    float2 bias0[NP];       // b_ih0 + b_hh0 paired
    float2 bias1[NP];
    float  wfc[2 * H];
    float  bfc[2];
    float  xs[DIN * XS_STRIDE]; // x tile for current timestep, [d][lane]
};

// ---------------- helpers ----------------
__device__ __forceinline__ ull ffma2(ull a, ull b, ull c) {
    ull d;
    asm("fma.rn.f32x2 %0, %1, %2, %3;" : "=l"(d) : "l"(a), "l"(b), "l"(c));
    return d;
}

__device__ __forceinline__ ull pack2(float x) {
    ull r;
    asm("mov.b64 %0, {%1, %1};" : "=l"(r) : "f"(x));
    return r;
}

__device__ __forceinline__ float getf(const ull* acc, int idx) {
    ull v = acc[idx >> 1];
    unsigned u = (idx & 1) ? (unsigned)(v >> 32) : (unsigned)(v & 0xffffffffu);
    return __uint_as_float(u);
}

__device__ __forceinline__ float sig_(float x) {
    // 1/(1+e^-x); MUFU.EX2 + MUFU.RCP. Robust: exp->inf gives rcp->0.
    return __fdividef(1.0f, 1.0f + __expf(-x));
}

__device__ __forceinline__ float tanh_(float x) {
    // sign-safe: tanh(x) = sign(x) * (1 - 2/(e^{2|x|}+1)); e->inf gives 1.
    float a = fabsf(x);
    float e = __expf(a + a);
    float r = 1.0f - __fdividef(2.0f, e + 1.0f);
    return copysignf(r, x);
}

// ---------------- kernel ----------------
__global__ void __launch_bounds__(CTA) lstm2_kernel(
    const float* __restrict__ x,
    const float* __restrict__ Wih0, const float* __restrict__ Whh0,
    const float* __restrict__ bih0, const float* __restrict__ bhh0,
    const float* __restrict__ Wih1, const float* __restrict__ Whh1,
    const float* __restrict__ bih1, const float* __restrict__ bhh1,
    const float* __restrict__ Wfc,  const float* __restrict__ bfc,
    float* __restrict__ out)
{
    extern __shared__ unsigned char smraw[];
    SM* sm = reinterpret_cast<SM*>(smraw);
    const int tid = threadIdx.x;

    // ---- stage weights into smem (transposed, gate-paired) ----
    for (int idx = tid; idx < DIN * NP; idx += CTA) {
        int d = idx / NP, j = idx - d * NP;
        sm->w0x[d * NP + j] = make_float2(Wih0[(2*j) * DIN + d], Wih0[(2*j+1) * DIN + d]);
    }
    for (int idx = tid; idx < H * NP; idx += CTA) {
        int k = idx / NP, j = idx - k * NP;
        sm->w0h[k * NP + j] = make_float2(Whh0[(2*j) * H + k], Whh0[(2*j+1) * H + k]);
        sm->w1x[k * NP + j] = make_float2(Wih1[(2*j) * H + k], Wih1[(2*j+1) * H + k]);
        sm->w1h[k * NP + j] = make_float2(Whh1[(2*j) * H + k], Whh1[(2*j+1) * H + k]);
    }
    for (int j = tid; j < NP; j += CTA) {
        sm->bias0[j] = make_float2(bih0[2*j] + bhh0[2*j], bih0[2*j+1] + bhh0[2*j+1]);
        sm->bias1[j] = make_float2(bih1[2*j] + bhh1[2*j], bih1[2*j+1] + bhh1[2*j+1]);
    }
    if (tid < 2 * H) sm->wfc[tid] = Wfc[tid];
    if (tid < 2)     sm->bfc[tid] = bfc[tid];

    const int b = blockIdx.x * CTA + tid;

    float h0[H], c0[H], h1[H], c1[H];
    #pragma unroll
    for (int k = 0; k < H; k++) { h0[k] = 0.f; c0[k] = 0.f; h1[k] = 0.f; c1[k] = 0.f; }

    const ull* w0x = reinterpret_cast<const ull*>(sm->w0x);
    const ull* w0h = reinterpret_cast<const ull*>(sm->w0h);
    const ull* w1x = reinterpret_cast<const ull*>(sm->w1x);
    const ull* w1h = reinterpret_cast<const ull*>(sm->w1h);
    const ull* bias0 = reinterpret_cast<const ull*>(sm->bias0);
    const ull* bias1 = reinterpret_cast<const ull*>(sm->bias1);

    const float* xblk = x + (size_t)blockIdx.x * CTA * T_STEPS * DIN;

    #pragma unroll 1
    for (int t = 0; t < T_STEPS; t++) {
        // ---- stage x[:, t, :] tile for this CTA's 128 batch rows ----
        __syncthreads();
        {
            const float* xt = xblk + t * DIN;
            for (int idx = tid; idx < CTA * DIN; idx += CTA) {
                int bl = idx / DIN, d = idx - bl * DIN;
                sm->xs[d * XS_STRIDE + bl] = xt[(size_t)bl * T_STEPS * DIN + d];
            }
        }
        __syncthreads();

        ull acc[NP];

        // ======== layer 0 ========
        #pragma unroll
        for (int j = 0; j < NP; j++) acc[j] = bias0[j];

        #pragma unroll 4
        for (int d = 0; d < DIN; d++) {
            ull xv = pack2(sm->xs[d * XS_STRIDE + tid]);
            const ull* wr = w0x + d * NP;
            #pragma unroll
            for (int j = 0; j < NP; j++) acc[j] = ffma2(wr[j], xv, acc[j]);
        }
        #pragma unroll
        for (int k = 0; k < H; k++) {
            ull hv = pack2(h0[k]);
            const ull* wr = w0h + k * NP;
            #pragma unroll
            for (int j = 0; j < NP; j++) acc[j] = ffma2(wr[j], hv, acc[j]);
        }
        #pragma unroll
        for (int k = 0; k < H; k++) {
            float iv = sig_ (getf(acc, k));
            float fv = sig_ (getf(acc, H + k));
            float gv = tanh_(getf(acc, 2*H + k));
            float ov = sig_ (getf(acc, 3*H + k));
            float c  = fv * c0[k] + iv * gv;
            c0[k] = c;
            h0[k] = ov * tanh_(c);
        }

        // ======== layer 1 (input = h0) ========
        #pragma unroll
        for (int j = 0; j < NP; j++) acc[j] = bias1[j];

        #pragma unroll
        for (int k = 0; k < H; k++) {
            ull xv = pack2(h0[k]);
            const ull* wr = w1x + k * NP;
            #pragma unroll
            for (int j = 0; j < NP; j++) acc[j] = ffma2(wr[j], xv, acc[j]);
        }
        #pragma unroll
        for (int k = 0; k < H; k++) {
            ull hv = pack2(h1[k]);
            const ull* wr = w1h + k * NP;
            #pragma unroll
            for (int j = 0; j < NP; j++) acc[j] = ffma2(wr[j], hv, acc[j]);
        }
        #pragma unroll
        for (int k = 0; k < H; k++) {
            float iv = sig_ (getf(acc, k));
            float fv = sig_ (getf(acc, H + k));
            float gv = tanh_(getf(acc, 2*H + k));
            float ov = sig_ (getf(acc, 3*H + k));
            float c  = fv * c1[k] + iv * gv;
            c1[k] = c;
            h1[k] = ov * tanh_(c);
        }
    }

    // ---- FC + softmax(2) ----
    float l0 = sm->bfc[0], l1 = sm->bfc[1];
    #pragma unroll
    for (int k = 0; k < H; k++) {
        l0 += sm->wfc[k]     * h1[k];
        l1 += sm->wfc[H + k] * h1[k];
    }
    float p0 = sig_(l0 - l1);           // = exp(l0)/(exp(l0)+exp(l1))
    reinterpret_cast<float2*>(out)[b] = make_float2(p0, 1.0f - p0);
}

// ---------------- launch ----------------
extern "C" void kernel_launch(void* const* d_in, const int* in_sizes, int n_in,
                              void* d_out, int out_size) {
    const float* x    = (const float*)d_in[0];
    const float* Wih0 = (const float*)d_in[1];
    const float* Whh0 = (const float*)d_in[2];
    const float* bih0 = (const float*)d_in[3];
    const float* bhh0 = (const float*)d_in[4];
    const float* Wih1 = (const float*)d_in[5];
    const float* Whh1 = (const float*)d_in[6];
    const float* bih1 = (const float*)d_in[7];
    const float* bhh1 = (const float*)d_in[8];
    const float* Wfc  = (const float*)d_in[9];
    const float* bfc  = (const float*)d_in[10];
    float* out = (float*)d_out;

    const size_t smem = sizeof(SM);
    cudaFuncSetAttribute(lstm2_kernel, cudaFuncAttributeMaxDynamicSharedMemorySize, (int)smem);

    lstm2_kernel<<<B_TOTAL / CTA, CTA, smem>>>(
        x, Wih0, Whh0, bih0, bhh0, Wih1, Whh1, bih1, bhh1, Wfc, bfc, out);
}

// round 2
// speedup vs baseline: 1.0028x; 1.0028x over previous
#include <cuda_runtime.h>
#include <cstdint>

typedef unsigned long long ull;

#define B_TOTAL 131072
#define T_STEPS 30
#define DIN     88
#define H       20
#define G       (4*H)     // 80 gate outputs
#define NP      (G/2)     // 40 packed fp32 pairs
#define NP2     (NP/2)    // 20 ulonglong2 (4 gate outputs) per dot-step
#define CTA     128
#define XS_STRIDE (CTA+1) // 129, bank-conflict-free

// ---------------- shared memory layout ----------------
struct __align__(16) SM {
    float2 w0x[DIN * NP];   // layer0 input weights, transposed+paired: [d][j] = (W[2j][d], W[2j+1][d])
    float2 w0h[H * NP];     // layer0 recurrent weights
    float2 w1x[H * NP];     // layer1 input (h0) weights
    float2 w1h[H * NP];     // layer1 recurrent weights
    float2 bias0[NP];       // b_ih0 + b_hh0 paired
    float2 bias1[NP];
    float  wfc[2 * H];
    float  bfc[2];
    float  xs[DIN * XS_STRIDE]; // x tile for current timestep, [d][lane]
};

// ---------------- helpers ----------------
__device__ __forceinline__ ull ffma2(ull a, ull b, ull c) {
    ull d;
    asm("fma.rn.f32x2 %0, %1, %2, %3;" : "=l"(d) : "l"(a), "l"(b), "l"(c));
    return d;
}

__device__ __forceinline__ ull pack2(float x) {
    ull r;
    asm("mov.b64 %0, {%1, %1};" : "=l"(r) : "f"(x));
    return r;
}

__device__ __forceinline__ float getf(const ull* acc, int idx) {
    ull v = acc[idx >> 1];
    unsigned u = (idx & 1) ? (unsigned)(v >> 32) : (unsigned)(v & 0xffffffffu);
    return __uint_as_float(u);
}

__device__ __forceinline__ float sig_(float x) {
    return __fdividef(1.0f, 1.0f + __expf(-x));
}

__device__ __forceinline__ float tanh_(float x) {
    float a = fabsf(x);
    float e = __expf(a + a);
    float r = 1.0f - __fdividef(2.0f, e + 1.0f);
    return copysignf(r, x);
}

// One dot-product step: acc[0..NP) += w_row[0..NP) * broadcast(v),
// weights fetched as LDS.128 (two packed pairs per load).
__device__ __forceinline__ void dot_step(ull* acc, const ulonglong2* wrow, ull v) {
    #pragma unroll
    for (int j = 0; j < NP2; j++) {
        ulonglong2 w = wrow[j];
        acc[2*j]   = ffma2(w.x, v, acc[2*j]);
        acc[2*j+1] = ffma2(w.y, v, acc[2*j+1]);
    }
}

// ---------------- kernel ----------------
__global__ void __launch_bounds__(CTA) lstm2_kernel(
    const float* __restrict__ x,
    const float* __restrict__ Wih0, const float* __restrict__ Whh0,
    const float* __restrict__ bih0, const float* __restrict__ bhh0,
    const float* __restrict__ Wih1, const float* __restrict__ Whh1,
    const float* __restrict__ bih1, const float* __restrict__ bhh1,
    const float* __restrict__ Wfc,  const float* __restrict__ bfc,
    float* __restrict__ out)
{
    extern __shared__ unsigned char smraw[];
    SM* sm = reinterpret_cast<SM*>(smraw);
    const int tid = threadIdx.x;

    // ---- stage weights into smem (transposed, gate-paired) ----
    for (int idx = tid; idx < DIN * NP; idx += CTA) {
        int d = idx / NP, j = idx - d * NP;
        sm->w0x[d * NP + j] = make_float2(Wih0[(2*j) * DIN + d], Wih0[(2*j+1) * DIN + d]);
    }
    for (int idx = tid; idx < H * NP; idx += CTA) {
        int k = idx / NP, j = idx - k * NP;
        sm->w0h[k * NP + j] = make_float2(Whh0[(2*j) * H + k], Whh0[(2*j+1) * H + k]);
        sm->w1x[k * NP + j] = make_float2(Wih1[(2*j) * H + k], Wih1[(2*j+1) * H + k]);
        sm->w1h[k * NP + j] = make_float2(Whh1[(2*j) * H + k], Whh1[(2*j+1) * H + k]);
    }
    for (int j = tid; j < NP; j += CTA) {
        sm->bias0[j] = make_float2(bih0[2*j] + bhh0[2*j], bih0[2*j+1] + bhh0[2*j+1]);
        sm->bias1[j] = make_float2(bih1[2*j] + bhh1[2*j], bih1[2*j+1] + bhh1[2*j+1]);
    }
    if (tid < 2 * H) sm->wfc[tid] = Wfc[tid];
    if (tid < 2)     sm->bfc[tid] = bfc[tid];

    const int b = blockIdx.x * CTA + tid;

    float h0[H], c0[H], h1[H], c1[H];
    #pragma unroll
    for (int k = 0; k < H; k++) { h0[k] = 0.f; c0[k] = 0.f; h1[k] = 0.f; c1[k] = 0.f; }

    const ulonglong2* w0x = reinterpret_cast<const ulonglong2*>(sm->w0x);
    const ulonglong2* w0h = reinterpret_cast<const ulonglong2*>(sm->w0h);
    const ulonglong2* w1x = reinterpret_cast<const ulonglong2*>(sm->w1x);
    const ulonglong2* w1h = reinterpret_cast<const ulonglong2*>(sm->w1h);
    const ull* bias0 = reinterpret_cast<const ull*>(sm->bias0);
    const ull* bias1 = reinterpret_cast<const ull*>(sm->bias1);

    const float* xblk = x + (size_t)blockIdx.x * CTA * T_STEPS * DIN;

    #pragma unroll 1
    for (int t = 0; t < T_STEPS; t++) {
        // ---- stage x[:, t, :] tile for this CTA's 128 batch rows ----
        __syncthreads();
        {
            const float* xt = xblk + t * DIN;
            for (int idx = tid; idx < CTA * DIN; idx += CTA) {
                int bl = idx / DIN, d = idx - bl * DIN;
                sm->xs[d * XS_STRIDE + bl] = xt[(size_t)bl * T_STEPS * DIN + d];
            }
        }
        __syncthreads();

        ull acc[NP];

        // ======== layer 0 ========
        #pragma unroll
        for (int j = 0; j < NP; j++) acc[j] = bias0[j];

        #pragma unroll 4
        for (int d = 0; d < DIN; d++) {
            ull xv = pack2(sm->xs[d * XS_STRIDE + tid]);
            dot_step(acc, w0x + d * NP2, xv);
        }
        #pragma unroll
        for (int k = 0; k < H; k++) {
            dot_step(acc, w0h + k * NP2, pack2(h0[k]));
        }
        #pragma unroll
        for (int k = 0; k < H; k++) {
            float iv = sig_ (getf(acc, k));
            float fv = sig_ (getf(acc, H + k));
            float gv = tanh_(getf(acc, 2*H + k));
            float ov = sig_ (getf(acc, 3*H + k));
            float c  = fv * c0[k] + iv * gv;
            c0[k] = c;
            h0[k] = ov * tanh_(c);
        }

        // ======== layer 1 (input = h0) ========
        #pragma unroll
        for (int j = 0; j < NP; j++) acc[j] = bias1[j];

        #pragma unroll
        for (int k = 0; k < H; k++) {
            dot_step(acc, w1x + k * NP2, pack2(h0[k]));
        }
        #pragma unroll
        for (int k = 0; k < H; k++) {
            dot_step(acc, w1h + k * NP2, pack2(h1[k]));
        }
        #pragma unroll
        for (int k = 0; k < H; k++) {
            float iv = sig_ (getf(acc, k));
            float fv = sig_ (getf(acc, H + k));
            float gv = tanh_(getf(acc, 2*H + k));
            float ov = sig_ (getf(acc, 3*H + k));
            float c  = fv * c1[k] + iv * gv;
            c1[k] = c;
            h1[k] = ov * tanh_(c);
        }
    }

    // ---- FC + softmax(2) ----
    float l0 = sm->bfc[0], l1 = sm->bfc[1];
    #pragma unroll
    for (int k = 0; k < H; k++) {
        l0 += sm->wfc[k]     * h1[k];
        l1 += sm->wfc[H + k] * h1[k];
    }
    float p0 = sig_(l0 - l1);           // = exp(l0)/(exp(l0)+exp(l1))
    reinterpret_cast<float2*>(out)[b] = make_float2(p0, 1.0f - p0);
}

// ---------------- launch ----------------
extern "C" void kernel_launch(void* const* d_in, const int* in_sizes, int n_in,
                              void* d_out, int out_size) {
    const float* x    = (const float*)d_in[0];
    const float* Wih0 = (const float*)d_in[1];
    const float* Whh0 = (const float*)d_in[2];
    const float* bih0 = (const float*)d_in[3];
    const float* bhh0 = (const float*)d_in[4];
    const float* Wih1 = (const float*)d_in[5];
    const float* Whh1 = (const float*)d_in[6];
    const float* bih1 = (const float*)d_in[7];
    const float* bhh1 = (const float*)d_in[8];
    const float* Wfc  = (const float*)d_in[9];
    const float* bfc  = (const float*)d_in[10];
    float* out = (float*)d_out;

    const size_t smem = sizeof(SM);
    cudaFuncSetAttribute(lstm2_kernel, cudaFuncAttributeMaxDynamicSharedMemorySize, (int)smem);

    lstm2_kernel<<<B_TOTAL / CTA, CTA, smem>>>(
        x, Wih0, Whh0, bih0, bhh0, Wih1, Whh1, bih1, bhh1, Wfc, bfc, out);
}

// round 3
// speedup vs baseline: 1.7809x; 1.7759x over previous
#include <cuda_runtime.h>
#include <cstdint>

typedef unsigned long long ull;

#define B_TOTAL 131072
#define T_STEPS 30
#define DIN     88
#define H       20
#define CTA     128
#define PAIRS   64          // CTA/2 thread-pairs; each pair = 2 batch elements
#define HS_STR  65          // hs row stride in float2 units (64 + 1 pad)

// ---------------- shared memory layout ----------------
// Weight float2 layout per input-dim d: 40 float2 ordered r = jj*4 + v*2 + pp,
// so ulonglong2 chunk index = d*20 + jj*2 + v  (v = lane parity = gate-half).
struct __align__(16) SM {
    float2 w0x[DIN * 40];   // 28160 B
    float2 w0h[H * 40];     // 6400 B
    float2 w1x[H * 40];     // 6400 B
    float2 w1h[H * 40];     // 6400 B
    float2 bias0[40];       // 320 B (b_ih0+b_hh0)
    float2 bias1[40];
    float  wfc[2 * H];
    float  bfc[2];
    float2 hs0[H * HS_STR]; // h state layer0: [k][pair] = (h[b0], h[b1])
    float2 hs1[H * HS_STR];
};

// ---------------- helpers ----------------
__device__ __forceinline__ ull ffma2(ull a, ull b, ull c) {
    ull d;
    asm("fma.rn.f32x2 %0, %1, %2, %3;" : "=l"(d) : "l"(a), "l"(b), "l"(c));
    return d;
}
__device__ __forceinline__ ull pack2(float x) {
    ull r;
    asm("mov.b64 %0, {%1, %1};" : "=l"(r) : "f"(x));
    return r;
}
__device__ __forceinline__ float getf(const ull* acc, int idx) {
    ull v = acc[idx >> 1];
    unsigned u = (idx & 1) ? (unsigned)(v >> 32) : (unsigned)(v & 0xffffffffu);
    return __uint_as_float(u);
}
__device__ __forceinline__ float sig_(float x) {
    return __fdividef(1.0f, 1.0f + __expf(-x));
}
__device__ __forceinline__ float tanh_(float x) {
    float a = fabsf(x);
    float e = __expf(a + a);
    float r = 1.0f - __fdividef(2.0f, e + 1.0f);
    return copysignf(r, x);
}

// acc += w_row * broadcast(x), for 2 batch elements, over this thread's
// 40 gate outputs (10 ulonglong2 chunks, stride 2 chunks = 32B).
__device__ __forceinline__ void accum_dim(ull* a0, ull* a1,
                                          const ulonglong2* __restrict__ wr,
                                          ull xv0, ull xv1) {
    #pragma unroll
    for (int jj = 0; jj < 10; jj++) {
        ulonglong2 w = wr[jj * 2];
        a0[2*jj]   = ffma2(w.x, xv0, a0[2*jj]);
        a0[2*jj+1] = ffma2(w.y, xv0, a0[2*jj+1]);
        a1[2*jj]   = ffma2(w.x, xv1, a1[2*jj]);
        a1[2*jj+1] = ffma2(w.y, xv1, a1[2*jj+1]);
    }
}

// LSTM pointwise for this thread's 10 gate rows of one batch element.
__device__ __forceinline__ void act(const ull* a, float* c, float* hout) {
    #pragma unroll
    for (int kl = 0; kl < 10; kl++) {
        float iv = sig_ (getf(a, kl));
        float fv = sig_ (getf(a, 10 + kl));
        float gv = tanh_(getf(a, 20 + kl));
        float ov = sig_ (getf(a, 30 + kl));
        float cn = fv * c[kl] + iv * gv;
        c[kl] = cn;
        hout[kl] = ov * tanh_(cn);
    }
}

// ---------------- kernel ----------------
__global__ void __launch_bounds__(CTA, 3) lstm2_kernel(
    const float* __restrict__ x,
    const float* __restrict__ Wih0, const float* __restrict__ Whh0,
    const float* __restrict__ bih0, const float* __restrict__ bhh0,
    const float* __restrict__ Wih1, const float* __restrict__ Whh1,
    const float* __restrict__ bih1, const float* __restrict__ bhh1,
    const float* __restrict__ Wfc,  const float* __restrict__ bfc,
    float* __restrict__ out)
{
    extern __shared__ unsigned char smraw[];
    SM* sm = reinterpret_cast<SM*>(smraw);
    const int tid = threadIdx.x;

    // ---- stage weights (transposed, gate-split-interleaved, paired) ----
    // r = jj*4 + v*2 + pp ; pair pp covers local outputs l = jj*4+pp*2, +1
    // local l -> global gate row g = (l/10)*20 + v*10 + (l%10)   [i,f,g,o x 20]
    #pragma unroll 1
    for (int idx = tid; idx < DIN * 40; idx += CTA) {
        int d = idx / 40, r = idx - d * 40;
        int jj = r >> 2, v = (r >> 1) & 1;
        int l0 = jj * 4 + (r & 1) * 2;
        int g0 = (l0 / 10) * 20 + v * 10 + (l0 % 10);
        int l1 = l0 + 1;
        int g1 = (l1 / 10) * 20 + v * 10 + (l1 % 10);
        sm->w0x[idx] = make_float2(Wih0[g0 * DIN + d], Wih0[g1 * DIN + d]);
    }
    #pragma unroll 1
    for (int idx = tid; idx < H * 40; idx += CTA) {
        int d = idx / 40, r = idx - d * 40;
        int jj = r >> 2, v = (r >> 1) & 1;
        int l0 = jj * 4 + (r & 1) * 2;
        int g0 = (l0 / 10) * 20 + v * 10 + (l0 % 10);
        int l1 = l0 + 1;
        int g1 = (l1 / 10) * 20 + v * 10 + (l1 % 10);
        sm->w0h[idx] = make_float2(Whh0[g0 * H + d], Whh0[g1 * H + d]);
        sm->w1x[idx] = make_float2(Wih1[g0 * H + d], Wih1[g1 * H + d]);
        sm->w1h[idx] = make_float2(Whh1[g0 * H + d], Whh1[g1 * H + d]);
    }
    if (tid < 40) {
        int r = tid;
        int jj = r >> 2, v = (r >> 1) & 1;
        int l0 = jj * 4 + (r & 1) * 2;
        int g0 = (l0 / 10) * 20 + v * 10 + (l0 % 10);
        int l1 = l0 + 1;
        int g1 = (l1 / 10) * 20 + v * 10 + (l1 % 10);
        sm->bias0[r] = make_float2(bih0[g0] + bhh0[g0], bih0[g1] + bhh0[g1]);
        sm->bias1[r] = make_float2(bih1[g0] + bhh1[g0], bih1[g1] + bhh1[g1]);
    }
    if (tid < 2 * H) sm->wfc[tid] = Wfc[tid];
    if (tid < 2)     sm->bfc[tid] = bfc[tid];

    const int p = tid >> 1;      // pair index 0..63
    const int v = tid & 1;       // gate-half

    // zero h state (each thread its own rows/col)
    #pragma unroll
    for (int kl = 0; kl < 10; kl++)
        sm->hs0[(v * 10 + kl) * HS_STR + p] = make_float2(0.f, 0.f);
    #pragma unroll
    for (int kl = 0; kl < 10; kl++)
        sm->hs1[(v * 10 + kl) * HS_STR + p] = make_float2(0.f, 0.f);
    __syncthreads();

    const int bg = blockIdx.x * CTA + 2 * p;          // global batch of elem 0
    const float* xr0 = x + (size_t)bg * T_STEPS * DIN;
    const float* xr1 = xr0 + T_STEPS * DIN;

    const ulonglong2* w0x = reinterpret_cast<const ulonglong2*>(sm->w0x);
    const ulonglong2* w0h = reinterpret_cast<const ulonglong2*>(sm->w0h);
    const ulonglong2* w1x = reinterpret_cast<const ulonglong2*>(sm->w1x);
    const ulonglong2* w1h = reinterpret_cast<const ulonglong2*>(sm->w1h);
    const ulonglong2* bias0 = reinterpret_cast<const ulonglong2*>(sm->bias0);
    const ulonglong2* bias1 = reinterpret_cast<const ulonglong2*>(sm->bias1);
    float2* hs0 = sm->hs0;
    float2* hs1 = sm->hs1;

    float c0a[10], c0b[10], c1a[10], c1b[10];
    #pragma unroll
    for (int kl = 0; kl < 10; kl++) { c0a[kl]=0.f; c0b[kl]=0.f; c1a[kl]=0.f; c1b[kl]=0.f; }

    ull a0[20], a1[20];

    #pragma unroll 1
    for (int t = 0; t < T_STEPS; t++) {
        // ================= layer 0 =================
        #pragma unroll
        for (int jj = 0; jj < 10; jj++) {
            ulonglong2 bb = bias0[jj * 2 + v];
            a0[2*jj] = bb.x; a0[2*jj+1] = bb.y;
            a1[2*jj] = bb.x; a1[2*jj+1] = bb.y;
        }
        // x contribution (direct global float4 loads)
        const float4* x0q = reinterpret_cast<const float4*>(xr0 + t * DIN);
        const float4* x1q = reinterpret_cast<const float4*>(xr1 + t * DIN);
        #pragma unroll 1
        for (int q = 0; q < DIN / 4; q++) {
            float4 xa = x0q[q];
            float4 xb = x1q[q];
            const ulonglong2* wrb = w0x + (q * 4) * 20 + v;
            accum_dim(a0, a1, wrb +  0, pack2(xa.x), pack2(xb.x));
            accum_dim(a0, a1, wrb + 20, pack2(xa.y), pack2(xb.y));
            accum_dim(a0, a1, wrb + 40, pack2(xa.z), pack2(xb.z));
            accum_dim(a0, a1, wrb + 60, pack2(xa.w), pack2(xb.w));
        }
        // recurrent h0 contribution
        #pragma unroll 2
        for (int k = 0; k < H; k++) {
            float2 hv = hs0[k * HS_STR + p];
            accum_dim(a0, a1, w0h + k * 20 + v, pack2(hv.x), pack2(hv.y));
        }
        {
            float h0a[10], h0b[10];
            act(a0, c0a, h0a);
            act(a1, c0b, h0b);
            #pragma unroll
            for (int kl = 0; kl < 10; kl++)
                hs0[(v * 10 + kl) * HS_STR + p] = make_float2(h0a[kl], h0b[kl]);
        }
        __syncwarp();

        // ================= layer 1 =================
        #pragma unroll
        for (int jj = 0; jj < 10; jj++) {
            ulonglong2 bb = bias1[jj * 2 + v];
            a0[2*jj] = bb.x; a0[2*jj+1] = bb.y;
            a1[2*jj] = bb.x; a1[2*jj+1] = bb.y;
        }
        #pragma unroll 2
        for (int k = 0; k < H; k++) {
            float2 hv = hs0[k * HS_STR + p];
            accum_dim(a0, a1, w1x + k * 20 + v, pack2(hv.x), pack2(hv.y));
        }
        #pragma unroll 2
        for (int k = 0; k < H; k++) {
            float2 hv = hs1[k * HS_STR + p];
            accum_dim(a0, a1, w1h + k * 20 + v, pack2(hv.x), pack2(hv.y));
        }
        {
            float h1a[10], h1b[10];
            act(a0, c1a, h1a);
            act(a1, c1b, h1b);
            #pragma unroll
            for (int kl = 0; kl < 10; kl++)
                hs1[(v * 10 + kl) * HS_STR + p] = make_float2(h1a[kl], h1b[kl]);
        }
        __syncwarp();
    }

    // ---- FC + softmax(2): thread v handles batch element (bg + v) ----
    float l0 = sm->bfc[0], l1 = sm->bfc[1];
    #pragma unroll
    for (int k = 0; k < H; k++) {
        float2 hv = hs1[k * HS_STR + p];
        float hk = v ? hv.y : hv.x;
        l0 += sm->wfc[k]     * hk;
        l1 += sm->wfc[H + k] * hk;
    }
    float p0 = sig_(l0 - l1);
    reinterpret_cast<float2*>(out)[bg + v] = make_float2(p0, 1.0f - p0);
}

// ---------------- launch ----------------
extern "C" void kernel_launch(void* const* d_in, const int* in_sizes, int n_in,
                              void* d_out, int out_size) {
    const float* x    = (const float*)d_in[0];
    const float* Wih0 = (const float*)d_in[1];
    const float* Whh0 = (const float*)d_in[2];
    const float* bih0 = (const float*)d_in[3];
    const float* bhh0 = (const float*)d_in[4];
    const float* Wih1 = (const float*)d_in[5];
    const float* Whh1 = (const float*)d_in[6];
    const float* bih1 = (const float*)d_in[7];
    const float* bhh1 = (const float*)d_in[8];
    const float* Wfc  = (const float*)d_in[9];
    const float* bfc  = (const float*)d_in[10];
    float* out = (float*)d_out;

    const size_t smem = sizeof(SM);
    cudaFuncSetAttribute(lstm2_kernel, cudaFuncAttributeMaxDynamicSharedMemorySize, (int)smem);

    lstm2_kernel<<<B_TOTAL / CTA, CTA, smem>>>(
        x, Wih0, Whh0, bih0, bhh0, Wih1, Whh1, bih1, bhh1, Wfc, bfc, out);
}

// round 4
// speedup vs baseline: 1.8846x; 1.0582x over previous
#include <cuda_runtime.h>
#include <cstdint>

typedef unsigned long long ull;

#define B_TOTAL 131072
#define T_STEPS 30
#define DIN     88
#define H       20
#define CTA     128
#define NGRP    32            // groups of 4 lanes per CTA; each group = 4 batch elems
#define HS_STR  33            // hs row stride in float4 units (32 groups + 1 pad)

// ---------------- shared memory layout ----------------
// Weight layout per matrix: float index [d*80 + v*20 + o], o = gate*5 + ul
// (gate 0..3 = i,f,g,o ; ul = unit within this lane's 5-unit slice).
// Global gate row for (v, o): (o/5)*20 + v*5 + (o%5).
// Read as ulonglong2 chunks: chunk (d, v, c) = outputs 4c..4c+3.
struct __align__(16) SM {
    float w0x[DIN * 80];    // 28160 B
    float w0h[H * 80];      // 6400 B
    float w1x[H * 80];      // 6400 B
    float w1h[H * 80];      // 6400 B
    float bias0[80];        // b_ih0 + b_hh0, same (v,o) layout
    float bias1[80];
    float wfc[2 * H];
    float bfc[2];
    float4 hs0[H * HS_STR]; // [unit][group] = h of the group's 4 elems
    float4 hs1[H * HS_STR];
};

// ---------------- helpers ----------------
__device__ __forceinline__ ull ffma2(ull a, ull b, ull c) {
    ull d;
    asm("fma.rn.f32x2 %0, %1, %2, %3;" : "=l"(d) : "l"(a), "l"(b), "l"(c));
    return d;
}
__device__ __forceinline__ ull pack2(float x) {
    ull r;
    asm("mov.b64 %0, {%1, %1};" : "=l"(r) : "f"(x));
    return r;
}
__device__ __forceinline__ float getf(const ull* acc, int idx) {
    ull v = acc[idx >> 1];
    unsigned u = (idx & 1) ? (unsigned)(v >> 32) : (unsigned)(v & 0xffffffffu);
    return __uint_as_float(u);
}
__device__ __forceinline__ float sig_(float x) {
    return __fdividef(1.0f, 1.0f + __expf(-x));
}
__device__ __forceinline__ float tanh_(float x) {
    float a = fabsf(x);
    float e = __expf(a + a);
    float r = 1.0f - __fdividef(2.0f, e + 1.0f);
    return copysignf(r, x);
}

// acc[e*10 + j] += w(d) * xv[e]; one dim, this lane's 20 outputs, 4 elems.
// 5 LDS.128, 40 FFMA2.
__device__ __forceinline__ void accum4(ull* a, const ulonglong2* __restrict__ w,
                                       ull x0, ull x1, ull x2, ull x3) {
    #pragma unroll
    for (int c = 0; c < 5; c++) {
        ulonglong2 wc = w[c];
        a[ 0 + 2*c]   = ffma2(wc.x, x0, a[ 0 + 2*c]);
        a[ 0 + 2*c+1] = ffma2(wc.y, x0, a[ 0 + 2*c+1]);
        a[10 + 2*c]   = ffma2(wc.x, x1, a[10 + 2*c]);
        a[10 + 2*c+1] = ffma2(wc.y, x1, a[10 + 2*c+1]);
        a[20 + 2*c]   = ffma2(wc.x, x2, a[20 + 2*c]);
        a[20 + 2*c+1] = ffma2(wc.y, x2, a[20 + 2*c+1]);
        a[30 + 2*c]   = ffma2(wc.x, x3, a[30 + 2*c]);
        a[30 + 2*c+1] = ffma2(wc.y, x3, a[30 + 2*c+1]);
    }
}

// ---------------- kernel ----------------
__global__ void __launch_bounds__(CTA, 3) lstm2_kernel(
    const float* __restrict__ x,
    const float* __restrict__ Wih0, const float* __restrict__ Whh0,
    const float* __restrict__ bih0, const float* __restrict__ bhh0,
    const float* __restrict__ Wih1, const float* __restrict__ Whh1,
    const float* __restrict__ bih1, const float* __restrict__ bhh1,
    const float* __restrict__ Wfc,  const float* __restrict__ bfc,
    float* __restrict__ out)
{
    extern __shared__ unsigned char smraw[];
    SM* sm = reinterpret_cast<SM*>(smraw);
    const int tid = threadIdx.x;

    // ---- stage weights: smem[d*80 + v*20 + o] = W[(o/5)*20 + v*5 + o%5][d] ----
    #pragma unroll 1
    for (int idx = tid; idx < DIN * 80; idx += CTA) {
        int d = idx / 80, rem = idx - d * 80;
        int v = rem / 20, o = rem - v * 20;
        int row = (o / 5) * 20 + v * 5 + (o % 5);
        sm->w0x[idx] = Wih0[row * DIN + d];
    }
    #pragma unroll 1
    for (int idx = tid; idx < H * 80; idx += CTA) {
        int d = idx / 80, rem = idx - d * 80;
        int v = rem / 20, o = rem - v * 20;
        int row = (o / 5) * 20 + v * 5 + (o % 5);
        sm->w0h[idx] = Whh0[row * H + d];
        sm->w1x[idx] = Wih1[row * H + d];
        sm->w1h[idx] = Whh1[row * H + d];
    }
    if (tid < 80) {
        int v = tid / 20, o = tid - v * 20;
        int row = (o / 5) * 20 + v * 5 + (o % 5);
        sm->bias0[tid] = bih0[row] + bhh0[row];
        sm->bias1[tid] = bih1[row] + bhh1[row];
    }
    if (tid < 2 * H) sm->wfc[tid] = Wfc[tid];
    if (tid < 2)     sm->bfc[tid] = bfc[tid];

    const int g = tid >> 2;      // group 0..31
    const int v = tid & 3;       // gate-quarter / unit-slice

    // zero h state: lane (g,v) owns units v*5..v*5+4 for its group's column
    #pragma unroll
    for (int ul = 0; ul < 5; ul++) {
        sm->hs0[(v * 5 + ul) * HS_STR + g] = make_float4(0.f, 0.f, 0.f, 0.f);
        sm->hs1[(v * 5 + ul) * HS_STR + g] = make_float4(0.f, 0.f, 0.f, 0.f);
    }
    __syncthreads();

    const int bg = blockIdx.x * CTA + g * 4;   // group's first batch elem
    const float4* xq0 = reinterpret_cast<const float4*>(x + (size_t)(bg + 0) * T_STEPS * DIN);
    const float4* xq1 = reinterpret_cast<const float4*>(x + (size_t)(bg + 1) * T_STEPS * DIN);
    const float4* xq2 = reinterpret_cast<const float4*>(x + (size_t)(bg + 2) * T_STEPS * DIN);
    const float4* xq3 = reinterpret_cast<const float4*>(x + (size_t)(bg + 3) * T_STEPS * DIN);

    const ulonglong2* w0x = reinterpret_cast<const ulonglong2*>(sm->w0x);
    const ulonglong2* w0h = reinterpret_cast<const ulonglong2*>(sm->w0h);
    const ulonglong2* w1x = reinterpret_cast<const ulonglong2*>(sm->w1x);
    const ulonglong2* w1h = reinterpret_cast<const ulonglong2*>(sm->w1h);
    const ulonglong2* bias0 = reinterpret_cast<const ulonglong2*>(sm->bias0) + v * 5;
    const ulonglong2* bias1 = reinterpret_cast<const ulonglong2*>(sm->bias1) + v * 5;
    float4* hs0 = sm->hs0;
    float4* hs1 = sm->hs1;

    float c0[20], c1[20];     // [e*5 + ul]
    #pragma unroll
    for (int i = 0; i < 20; i++) { c0[i] = 0.f; c1[i] = 0.f; }

    ull a[40];                // [e*10 + pair]

    #pragma unroll 1
    for (int t = 0; t < T_STEPS; t++) {
        const int qb = t * (DIN / 4);

        // ================= layer 0 =================
        #pragma unroll
        for (int c = 0; c < 5; c++) {
            ulonglong2 bb = bias0[c];
            a[2*c] = bb.x; a[2*c+1] = bb.y;
            a[10+2*c] = bb.x; a[10+2*c+1] = bb.y;
            a[20+2*c] = bb.x; a[20+2*c+1] = bb.y;
            a[30+2*c] = bb.x; a[30+2*c+1] = bb.y;
        }
        #pragma unroll 2
        for (int q = 0; q < DIN / 4; q++) {
            float4 xa = xq0[qb + q];
            float4 xb = xq1[qb + q];
            float4 xc = xq2[qb + q];
            float4 xd = xq3[qb + q];
            const ulonglong2* wb = w0x + (q * 4) * 20 + v * 5;
            accum4(a, wb +  0, pack2(xa.x), pack2(xb.x), pack2(xc.x), pack2(xd.x));
            accum4(a, wb + 20, pack2(xa.y), pack2(xb.y), pack2(xc.y), pack2(xd.y));
            accum4(a, wb + 40, pack2(xa.z), pack2(xb.z), pack2(xc.z), pack2(xd.z));
            accum4(a, wb + 60, pack2(xa.w), pack2(xb.w), pack2(xc.w), pack2(xd.w));
        }
        #pragma unroll 4
        for (int k = 0; k < H; k++) {
            float4 hv = hs0[k * HS_STR + g];
            accum4(a, w0h + k * 20 + v * 5,
                   pack2(hv.x), pack2(hv.y), pack2(hv.z), pack2(hv.w));
        }
        // activations + h0 write (unit-major so each unit stores one float4)
        #pragma unroll
        for (int ul = 0; ul < 5; ul++) {
            float hv[4];
            #pragma unroll
            for (int e = 0; e < 4; e++) {
                const ull* ae = a + e * 10;
                float iv = sig_ (getf(ae,      ul));
                float fv = sig_ (getf(ae,  5 + ul));
                float gv = tanh_(getf(ae, 10 + ul));
                float ov = sig_ (getf(ae, 15 + ul));
                float cn = fv * c0[e*5 + ul] + iv * gv;
                c0[e*5 + ul] = cn;
                hv[e] = ov * tanh_(cn);
            }
            hs0[(v * 5 + ul) * HS_STR + g] = make_float4(hv[0], hv[1], hv[2], hv[3]);
        }
        __syncwarp();

        // ================= layer 1 =================
        #pragma unroll
        for (int c = 0; c < 5; c++) {
            ulonglong2 bb = bias1[c];
            a[2*c] = bb.x; a[2*c+1] = bb.y;
            a[10+2*c] = bb.x; a[10+2*c+1] = bb.y;
            a[20+2*c] = bb.x; a[20+2*c+1] = bb.y;
            a[30+2*c] = bb.x; a[30+2*c+1] = bb.y;
        }
        #pragma unroll 4
        for (int k = 0; k < H; k++) {
            float4 hv = hs0[k * HS_STR + g];
            accum4(a, w1x + k * 20 + v * 5,
                   pack2(hv.x), pack2(hv.y), pack2(hv.z), pack2(hv.w));
        }
        #pragma unroll 4
        for (int k = 0; k < H; k++) {
            float4 hv = hs1[k * HS_STR + g];
            accum4(a, w1h + k * 20 + v * 5,
                   pack2(hv.x), pack2(hv.y), pack2(hv.z), pack2(hv.w));
        }
        #pragma unroll
        for (int ul = 0; ul < 5; ul++) {
            float hv[4];
            #pragma unroll
            for (int e = 0; e < 4; e++) {
                const ull* ae = a + e * 10;
                float iv = sig_ (getf(ae,      ul));
                float fv = sig_ (getf(ae,  5 + ul));
                float gv = tanh_(getf(ae, 10 + ul));
                float ov = sig_ (getf(ae, 15 + ul));
                float cn = fv * c1[e*5 + ul] + iv * gv;
                c1[e*5 + ul] = cn;
                hv[e] = ov * tanh_(cn);
            }
            hs1[(v * 5 + ul) * HS_STR + g] = make_float4(hv[0], hv[1], hv[2], hv[3]);
        }
        __syncwarp();
    }

    // ---- FC + softmax(2): lane v handles its group's elem v ----
    float l0 = sm->bfc[0], l1 = sm->bfc[1];
    #pragma unroll
    for (int k = 0; k < H; k++) {
        float4 hq = hs1[k * HS_STR + g];
        float hk = (v == 0) ? hq.x : (v == 1) ? hq.y : (v == 2) ? hq.z : hq.w;
        l0 += sm->wfc[k]     * hk;
        l1 += sm->wfc[H + k] * hk;
    }
    float p0 = sig_(l0 - l1);
    reinterpret_cast<float2*>(out)[bg + v] = make_float2(p0, 1.0f - p0);
}

// ---------------- launch ----------------
extern "C" void kernel_launch(void* const* d_in, const int* in_sizes, int n_in,
                              void* d_out, int out_size) {
    const float* x    = (const float*)d_in[0];
    const float* Wih0 = (const float*)d_in[1];
    const float* Whh0 = (const float*)d_in[2];
    const float* bih0 = (const float*)d_in[3];
    const float* bhh0 = (const float*)d_in[4];
    const float* Wih1 = (const float*)d_in[5];
    const float* Whh1 = (const float*)d_in[6];
    const float* bih1 = (const float*)d_in[7];
    const float* bhh1 = (const float*)d_in[8];
    const float* Wfc  = (const float*)d_in[9];
    const float* bfc  = (const float*)d_in[10];
    float* out = (float*)d_out;

    const size_t smem = sizeof(SM);
    cudaFuncSetAttribute(lstm2_kernel, cudaFuncAttributeMaxDynamicSharedMemorySize, (int)smem);

    lstm2_kernel<<<B_TOTAL / CTA, CTA, smem>>>(
        x, Wih0, Whh0, bih0, bhh0, Wih1, Whh1, bih1, bhh1, Wfc, bfc, out);
}